// round 11
// baseline (speedup 1.0000x reference)
#include <cuda_runtime.h>
#include <cuda_fp16.h>
#include <cuda_bf16.h>
#include <stdint.h>

#define EDIM 128
#define TROWS 140      // 10 dev + 10 pseudo + 100 attr + 20 unit
#define OUTD 768
#define MAXROWS 131072

// ---------------- persistent scratch (rewritten every launch) ----------------
__device__ __half g_Pqh[TROWS * EDIM];    // tables @ Wq^T (fp16)
__device__ __half g_Pkh[TROWS * EDIM];    // tables @ Wk^T (fp16)
__device__ __half g_Pvh[TROWS * EDIM];    // tables @ Wv^T (fp16)
__device__ __half g_Avh[3 * EDIM];        // W_qkv @ val_w (fp16)
__device__ __half g_Bvh[3 * EDIM];        // W_qkv @ val_b (fp16)
__device__ __half g_W2[OUTD * EDIM];      // out_w @ out_proj_w  (fp16)
__device__ float  g_b2[OUTD];             // out_w @ out_proj_b + out_b

// ---------------- setup 1: project the 4 embedding tables through in_proj ----------------
__global__ void setup_tables(const float* __restrict__ dev_t, const float* __restrict__ pse_t,
                             const float* __restrict__ attr_t, const float* __restrict__ unit_t,
                             const float* __restrict__ W) {
    __shared__ float row[EDIM];
    int b = blockIdx.x, t = threadIdx.x;
    const float* src; int r;
    if (b < 10)       { src = dev_t;  r = b; }
    else if (b < 20)  { src = pse_t;  r = b - 10; }
    else if (b < 120) { src = attr_t; r = b - 20; }
    else              { src = unit_t; r = b - 120; }
    row[t] = src[r * EDIM + t];
    __syncthreads();
    float aq = 0.f, ak = 0.f, av = 0.f;
    const float* wq = W + t * EDIM;
    const float* wk = W + (EDIM + t) * EDIM;
    const float* wv = W + (2 * EDIM + t) * EDIM;
    #pragma unroll 4
    for (int c = 0; c < EDIM; ++c) {
        float rc = row[c];
        aq = fmaf(rc, wq[c], aq);
        ak = fmaf(rc, wk[c], ak);
        av = fmaf(rc, wv[c], av);
    }
    g_Pqh[b * EDIM + t] = __float2half_rn(aq);
    g_Pkh[b * EDIM + t] = __float2half_rn(ak);
    g_Pvh[b * EDIM + t] = __float2half_rn(av);
}

// ---------------- setup 2: value-token projection vectors ----------------
__global__ void setup_valproj(const float* __restrict__ val_w, const float* __restrict__ val_b,
                              const float* __restrict__ W) {
    __shared__ float vw[EDIM], vb[EDIM];
    int t = threadIdx.x;                 // 0..383
    if (t < EDIM) { vw[t] = val_w[t]; vb[t] = val_b[t]; }
    __syncthreads();
    float a = 0.f, bb = 0.f;
    const float* wr = W + t * EDIM;
    #pragma unroll 4
    for (int c = 0; c < EDIM; ++c) {
        a  = fmaf(vw[c], wr[c], a);
        bb = fmaf(vb[c], wr[c], bb);
    }
    g_Avh[t] = __float2half_rn(a);
    g_Bvh[t] = __float2half_rn(bb);
}

// ---------------- setup 3: fold out_proj into out_w ----------------
__global__ void setup_w2(const float* __restrict__ out_w, const float* __restrict__ out_proj_w,
                         const float* __restrict__ out_proj_b, const float* __restrict__ out_b) {
    __shared__ float wrow[EDIM];
    __shared__ float red[EDIM];
    int o = blockIdx.x, t = threadIdx.x;
    wrow[t] = out_w[o * EDIM + t];
    __syncthreads();
    float acc = 0.f;
    #pragma unroll 4
    for (int m = 0; m < EDIM; ++m)
        acc = fmaf(wrow[m], out_proj_w[m * EDIM + t], acc);
    g_W2[o * EDIM + t] = __float2half_rn(acc);
    red[t] = wrow[t] * out_proj_b[t];
    __syncthreads();
    #pragma unroll
    for (int s = 64; s > 0; s >>= 1) {
        if (t < s) red[t] += red[t + s];
        __syncthreads();
    }
    if (t == 0) g_b2[o] = out_b[o] + red[0];
}

__device__ __forceinline__ float4 ldg4(const float* p) {
    return *reinterpret_cast<const float4*>(p);
}
// 4 halves -> 4 floats (8-byte load)
__device__ __forceinline__ void ldh4(const __half* p, float* f) {
    uint2 u = *reinterpret_cast<const uint2*>(p);
    __half2 h0 = *reinterpret_cast<__half2*>(&u.x);
    __half2 h1 = *reinterpret_cast<__half2*>(&u.y);
    float2 a = __half22float2(h0); f[0] = a.x; f[1] = a.y;
    float2 b = __half22float2(h1); f[2] = b.x; f[3] = b.y;
}
__device__ __forceinline__ void cp16(uint32_t dst, const void* src) {
    asm volatile("cp.async.cg.shared.global [%0], [%1], 16;" :: "r"(dst), "l"(src));
}

// ---------------- fused kernel: gather + MHA -> smem A tile -> fp16 mma -> out ----------------
// grid ceil(N/128); block 256 = 8 warps.
// smem layout (halves): A[128*BPITCH], then B double buffer 2 x [128*BPITCH].
#define BPITCH 136                          // halves per smem row (272 B)
#define SM_A_H 0
#define SM_B_H (128 * BPITCH)
#define FUSED_SMEM ((128 * BPITCH + 2 * 128 * BPITCH) * 2)   // 104448 bytes

__global__ void __launch_bounds__(256, 2)
fused_kernel(const int* __restrict__ dev_ids, const int* __restrict__ pse_ids,
             const int* __restrict__ attr_ids, const int* __restrict__ unit_ids,
             const float* __restrict__ values, const int* __restrict__ mask,
             const float* __restrict__ in_proj_b,
             float* __restrict__ out, int N) {
    extern __shared__ __align__(16) __half S[];
    int tid = threadIdx.x;
    int warp = tid >> 5, lane = tid & 31;
    int m0 = blockIdx.x * 128;
    uint32_t sbase = (uint32_t)__cvta_generic_to_shared(S);

    // ---- issue cp.async for B tile 0 (overlaps the entire attention phase) ----
    {
        #pragma unroll
        for (int i = 0; i < 8; ++i) {
            int idx = tid + i * 256;              // 0..2047 (128 rows x 16 chunks)
            int srow = idx >> 4, schunk = idx & 15;
            const __half* src = g_W2 + (size_t)srow * EDIM + schunk * 8;
            uint32_t dst = sbase + (uint32_t)((SM_B_H + srow * BPITCH + schunk * 8) * 2);
            cp16(dst, src);
        }
        asm volatile("cp.async.commit_group;" ::: "memory");
    }

    // ---- attention phase: this warp computes rows m0+warp*16 .. +15 into smem A ----
    {
        int d0 = lane * 4;
        int tOwn = lane & 7;
        float bq[4], bk[4], bv[4];
        { float4 t4 = ldg4(in_proj_b + d0);            bq[0]=t4.x; bq[1]=t4.y; bq[2]=t4.z; bq[3]=t4.w; }
        { float4 t4 = ldg4(in_proj_b + EDIM + d0);     bk[0]=t4.x; bk[1]=t4.y; bk[2]=t4.z; bk[3]=t4.w; }
        { float4 t4 = ldg4(in_proj_b + 2 * EDIM + d0); bv[0]=t4.x; bv[1]=t4.y; bv[2]=t4.z; bv[3]=t4.w; }
        // value-token projection vectors (row-independent): load once
        float Aq[4], Ak[4], Av_[4], Zq[4], Zk[4], Zv[4];
        ldh4(g_Avh + d0, Aq);
        ldh4(g_Avh + EDIM + d0, Ak);
        ldh4(g_Avh + 2 * EDIM + d0, Av_);
        ldh4(g_Bvh + d0, Zq);
        ldh4(g_Bvh + EDIM + d0, Zk);
        ldh4(g_Bvh + 2 * EDIM + d0, Zv);

        for (int i = 0; i < 16; ++i) {
            int lrow = warp * 16 + i;
            int n = m0 + lrow;
            float ao0 = 0.f, ao1 = 0.f, ao2 = 0.f, ao3 = 0.f;
            if (n < N) {
                float mm[5];
                #pragma unroll
                for (int t = 0; t < 5; ++t) mm[t] = (float)mask[n * 5 + t];
                int r0 = dev_ids[n];
                int r1 = 10  + pse_ids[n];
                int r2 = 20  + attr_ids[n];
                int r3 = 120 + unit_ids[n];
                float val = values[n];

                float q[5][4], k[5][4], v[5][4];
                const int ridx[4] = {r0, r1, r2, r3};
                const int tok[4] = {0, 1, 2, 4};
                #pragma unroll
                for (int ii = 0; ii < 4; ++ii) {
                    int t = tok[ii];
                    float pq[4], pk[4], pv[4];
                    ldh4(g_Pqh + ridx[ii] * EDIM + d0, pq);
                    ldh4(g_Pkh + ridx[ii] * EDIM + d0, pk);
                    ldh4(g_Pvh + ridx[ii] * EDIM + d0, pv);
                    float mt = mm[t];
                    #pragma unroll
                    for (int c = 0; c < 4; ++c) {
                        q[t][c] = fmaf(mt, pq[c], bq[c]);
                        k[t][c] = fmaf(mt, pk[c], bk[c]);
                        v[t][c] = fmaf(mt, pv[c], bv[c]);
                    }
                }
                {   // value token (t = 3)
                    float m3 = mm[3];
                    #pragma unroll
                    for (int c = 0; c < 4; ++c) {
                        q[3][c] = fmaf(m3, fmaf(val, Aq[c],  Zq[c]), bq[c]);
                        k[3][c] = fmaf(m3, fmaf(val, Ak[c],  Zk[c]), bk[c]);
                        v[3][c] = fmaf(m3, fmaf(val, Av_[c], Zv[c]), bv[c]);
                    }
                }

                // scores per head (8-lane butterfly); lane keeps only its own t-row
                float scr[5] = {0.f, 0.f, 0.f, 0.f, 0.f};
                #pragma unroll
                for (int t = 0; t < 5; ++t) {
                    #pragma unroll
                    for (int s = 0; s < 5; ++s) {
                        float p = q[t][0] * k[s][0] + q[t][1] * k[s][1]
                                + q[t][2] * k[s][2] + q[t][3] * k[s][3];
                        p += __shfl_xor_sync(0xffffffffu, p, 1);
                        p += __shfl_xor_sync(0xffffffffu, p, 2);
                        p += __shfl_xor_sync(0xffffffffu, p, 4);
                        scr[s] = (tOwn == t) ? p * 0.17677669529663687f : scr[s]; // 1/sqrt(32)
                    }
                }
                // distributed softmax (lanes 0..4 of each 8-group own one t)
                float w[5] = {0.f, 0.f, 0.f, 0.f, 0.f};
                if (tOwn < 5) {
                    float mx = scr[0];
                    #pragma unroll
                    for (int s = 1; s < 5; ++s) mx = fmaxf(mx, scr[s]);
                    float e[5], sum = 0.f;
                    #pragma unroll
                    for (int s = 0; s < 5; ++s) { e[s] = __expf(scr[s] - mx); sum += e[s]; }
                    float inv = __fdividef(1.f, sum);
                    #pragma unroll
                    for (int s = 0; s < 5; ++s) w[s] = e[s] * inv;
                }
                #pragma unroll
                for (int s = 0; s < 5; ++s) {
                    w[s] += __shfl_xor_sync(0xffffffffu, w[s], 1);
                    w[s] += __shfl_xor_sync(0xffffffffu, w[s], 2);
                    w[s] += __shfl_xor_sync(0xffffffffu, w[s], 4);
                }
                #pragma unroll
                for (int s = 0; s < 5; ++s) {
                    float ws = w[s] * 0.2f;
                    ao0 = fmaf(ws, v[s][0], ao0);
                    ao1 = fmaf(ws, v[s][1], ao1);
                    ao2 = fmaf(ws, v[s][2], ao2);
                    ao3 = fmaf(ws, v[s][3], ao3);
                }
            }
            __half2 h01 = __floats2half2_rn(ao0, ao1);
            __half2 h23 = __floats2half2_rn(ao2, ao3);
            uint2 st;
            st.x = *reinterpret_cast<uint32_t*>(&h01);
            st.y = *reinterpret_cast<uint32_t*>(&h23);
            *reinterpret_cast<uint2*>(&S[SM_A_H + lrow * BPITCH + d0]) = st;
        }
        __syncwarp();   // A rows of this warp visible to all its lanes
    }

    // ---- load A fragments from smem (warp reads only its OWN 16 rows) ----
    int g = lane >> 2;            // 0..7
    int tq = lane & 3;            // 0..3
    int mrow = m0 + warp * 16 + g;
    uint32_t a[8][4];
    {
        const __half* Ab = &S[SM_A_H + (warp * 16 + g) * BPITCH];
        #pragma unroll
        for (int s = 0; s < 8; ++s) {
            int kk = s * 16 + tq * 2;
            a[s][0] = *reinterpret_cast<const uint32_t*>(Ab + kk);
            a[s][1] = *reinterpret_cast<const uint32_t*>(Ab + 8 * BPITCH + kk);
            a[s][2] = *reinterpret_cast<const uint32_t*>(Ab + kk + 8);
            a[s][3] = *reinterpret_cast<const uint32_t*>(Ab + 8 * BPITCH + kk + 8);
        }
    }

    // ldmatrix lane addressing: 4 8x8 matrices per x4
    int brow = ((lane >> 4) << 3) + (lane & 7);   // n-row within 16-row jpair
    int bk_  = ((lane >> 3) & 1) * 8;             // k sub-offset

    // ---- GEMM loop: 6 N-tiles of 128, double-buffered B ----
    for (int nt = 0; nt < 6; ++nt) {
        asm volatile("cp.async.wait_group 0;" ::: "memory");
        __syncthreads();
        uint32_t cur = sbase + (uint32_t)((SM_B_H + (nt & 1) * 128 * BPITCH) * 2);

        // prefetch next tile into the other buffer
        if (nt < 5) {
            #pragma unroll
            for (int i = 0; i < 8; ++i) {
                int idx = tid + i * 256;
                int srow = idx >> 4, schunk = idx & 15;
                const __half* src = g_W2 + (size_t)(nt + 1) * 128 * EDIM
                                    + (size_t)srow * EDIM + schunk * 8;
                uint32_t dst = sbase + (uint32_t)((SM_B_H + ((nt + 1) & 1) * 128 * BPITCH
                                                  + srow * BPITCH + schunk * 8) * 2);
                cp16(dst, src);
            }
            asm volatile("cp.async.commit_group;" ::: "memory");
        }

        float acc[16][4];
        #pragma unroll
        for (int j = 0; j < 16; ++j)
            #pragma unroll
            for (int c = 0; c < 4; ++c) acc[j][c] = 0.f;

        #pragma unroll
        for (int s = 0; s < 8; ++s) {
            #pragma unroll
            for (int jp = 0; jp < 8; ++jp) {
                uint32_t b0, b1, b2, b3;
                uint32_t addr = cur +
                    (uint32_t)(((jp * 16 + brow) * BPITCH + s * 16 + bk_) * 2);
                asm volatile(
                    "ldmatrix.sync.aligned.m8n8.x4.shared.b16 {%0,%1,%2,%3}, [%4];"
                    : "=r"(b0), "=r"(b1), "=r"(b2), "=r"(b3) : "r"(addr));
                asm volatile(
                    "mma.sync.aligned.m16n8k16.row.col.f32.f16.f16.f32 "
                    "{%0,%1,%2,%3}, {%4,%5,%6,%7}, {%8,%9}, {%0,%1,%2,%3};"
                    : "+f"(acc[2 * jp][0]), "+f"(acc[2 * jp][1]),
                      "+f"(acc[2 * jp][2]), "+f"(acc[2 * jp][3])
                    : "r"(a[s][0]), "r"(a[s][1]), "r"(a[s][2]), "r"(a[s][3]),
                      "r"(b0), "r"(b1));
                asm volatile(
                    "mma.sync.aligned.m16n8k16.row.col.f32.f16.f16.f32 "
                    "{%0,%1,%2,%3}, {%4,%5,%6,%7}, {%8,%9}, {%0,%1,%2,%3};"
                    : "+f"(acc[2 * jp + 1][0]), "+f"(acc[2 * jp + 1][1]),
                      "+f"(acc[2 * jp + 1][2]), "+f"(acc[2 * jp + 1][3])
                    : "r"(a[s][0]), "r"(a[s][1]), "r"(a[s][2]), "r"(a[s][3]),
                      "r"(b2), "r"(b3));
            }
        }

        // epilogue: add b2, store (c0,c1 = row g cols 2tq..; c2,c3 = row g+8)
        int ccol = tq * 2;
        int n0 = nt * 128;
        bool ok0 = (mrow < N), ok1 = (mrow + 8 < N);
        #pragma unroll
        for (int j = 0; j < 16; ++j) {
            int col = n0 + j * 8 + ccol;
            float2 bb = *reinterpret_cast<const float2*>(g_b2 + col);
            float2 q0 = make_float2(acc[j][0] + bb.x, acc[j][1] + bb.y);
            float2 q1 = make_float2(acc[j][2] + bb.x, acc[j][3] + bb.y);
            if (ok0) *reinterpret_cast<float2*>(out + (size_t)mrow * OUTD + col) = q0;
            if (ok1) *reinterpret_cast<float2*>(out + (size_t)(mrow + 8) * OUTD + col) = q1;
        }
        __syncthreads();   // all reads of this B buffer done before it is overwritten
    }
}

extern "C" void kernel_launch(void* const* d_in, const int* in_sizes, int n_in,
                              void* d_out, int out_size) {
    (void)n_in; (void)out_size;
    const int*   dev_ids    = (const int*)  d_in[0];
    const int*   pse_ids    = (const int*)  d_in[1];
    const int*   attr_ids   = (const int*)  d_in[2];
    const int*   unit_ids   = (const int*)  d_in[3];
    const float* values     = (const float*)d_in[4];
    const int*   mask       = (const int*)  d_in[5];
    const float* dev_t      = (const float*)d_in[6];
    const float* pse_t      = (const float*)d_in[7];
    const float* attr_t     = (const float*)d_in[8];
    const float* unit_t     = (const float*)d_in[9];
    const float* val_w      = (const float*)d_in[10];
    const float* val_b      = (const float*)d_in[11];
    const float* in_proj_w  = (const float*)d_in[12];
    const float* in_proj_b  = (const float*)d_in[13];
    const float* out_proj_w = (const float*)d_in[14];
    const float* out_proj_b = (const float*)d_in[15];
    const float* out_w      = (const float*)d_in[16];
    const float* out_b      = (const float*)d_in[17];
    float* out = (float*)d_out;
    int N = in_sizes[0];
    if (N > MAXROWS) N = MAXROWS;

    cudaFuncSetAttribute(fused_kernel, cudaFuncAttributeMaxDynamicSharedMemorySize, FUSED_SMEM);

    setup_tables<<<TROWS, EDIM>>>(dev_t, pse_t, attr_t, unit_t, in_proj_w);
    setup_valproj<<<1, 3 * EDIM>>>(val_w, val_b, in_proj_w);
    setup_w2<<<OUTD, EDIM>>>(out_w, out_proj_w, out_proj_b, out_b);
    fused_kernel<<<(N + 127) / 128, 256, FUSED_SMEM>>>(
        dev_ids, pse_ids, attr_ids, unit_ids, values, mask, in_proj_b, out, N);
}

// round 14
// speedup vs baseline: 1.1053x; 1.1053x over previous
#include <cuda_runtime.h>
#include <cuda_fp16.h>
#include <cuda_bf16.h>
#include <stdint.h>

#define EDIM 128
#define TROWS 140      // 10 dev + 10 pseudo + 100 attr + 20 unit
#define OUTD 768
#define MAXROWS 131072

// ---------------- persistent scratch (rewritten every launch) ----------------
__device__ __half g_Pqh[TROWS * EDIM];    // tables @ Wq^T (fp16)
__device__ __half g_Pkh[TROWS * EDIM];    // tables @ Wk^T (fp16)
__device__ __half g_Pvh[TROWS * EDIM];    // tables @ Wv^T (fp16)
__device__ __half g_Avh[3 * EDIM];        // W_qkv @ val_w (fp16)
__device__ __half g_Bvh[3 * EDIM];        // W_qkv @ val_b (fp16)
__device__ __half g_W2[OUTD * EDIM];      // out_w @ out_proj_w  (fp16)
__device__ float  g_b2[OUTD];             // out_w @ out_proj_b + out_b

// ---------------- merged setup kernel ----------------
// blocks [0, TROWS)        : embedding tables through in_proj (384 thr = 3 proj x 128 col)
// block  TROWS             : value-token projection vectors
// blocks (TROWS, TROWS+256]: fold out_proj into out_w (3 output rows per block)
__global__ void __launch_bounds__(384)
setup_all(const float* __restrict__ dev_t, const float* __restrict__ pse_t,
          const float* __restrict__ attr_t, const float* __restrict__ unit_t,
          const float* __restrict__ W,
          const float* __restrict__ val_w, const float* __restrict__ val_b,
          const float* __restrict__ out_w, const float* __restrict__ out_proj_w,
          const float* __restrict__ out_proj_b, const float* __restrict__ out_b) {
    __shared__ float sm[768];
    int b = blockIdx.x, t = threadIdx.x;

    if (b < TROWS) {
        const float* src; int r;
        if (b < 10)       { src = dev_t;  r = b; }
        else if (b < 20)  { src = pse_t;  r = b - 10; }
        else if (b < 120) { src = attr_t; r = b - 20; }
        else              { src = unit_t; r = b - 120; }
        if (t < 128) sm[t] = src[r * EDIM + t];
        __syncthreads();
        int col = t & 127, which = t >> 7;   // which: 0=q, 1=k, 2=v
        const float* wr = W + (size_t)(which * EDIM + col) * EDIM;
        float acc = 0.f;
        #pragma unroll 4
        for (int c = 0; c < EDIM; ++c) acc = fmaf(sm[c], wr[c], acc);
        __half hv = __float2half_rn(acc);
        if (which == 0)      g_Pqh[b * EDIM + col] = hv;
        else if (which == 1) g_Pkh[b * EDIM + col] = hv;
        else                 g_Pvh[b * EDIM + col] = hv;
    } else if (b == TROWS) {
        float* vw = sm; float* vb = sm + 128;
        if (t < 128) { vw[t] = val_w[t]; vb[t] = val_b[t]; }
        __syncthreads();
        float a = 0.f, bb = 0.f;
        const float* wr = W + (size_t)t * EDIM;
        #pragma unroll 4
        for (int c = 0; c < EDIM; ++c) {
            a  = fmaf(vw[c], wr[c], a);
            bb = fmaf(vb[c], wr[c], bb);
        }
        g_Avh[t] = __float2half_rn(a);
        g_Bvh[t] = __float2half_rn(bb);
    } else {
        int grp = t >> 7, tt = t & 127;
        int o = (b - TROWS - 1) * 3 + grp;        // 0..767
        float* wrow = sm;            // [3][128]
        float* red  = sm + 384;      // [3][128]
        wrow[grp * 128 + tt] = out_w[(size_t)o * EDIM + tt];
        __syncthreads();
        float acc = 0.f;
        #pragma unroll 4
        for (int m = 0; m < EDIM; ++m)
            acc = fmaf(wrow[grp * 128 + m], out_proj_w[(size_t)m * EDIM + tt], acc);
        g_W2[(size_t)o * EDIM + tt] = __float2half_rn(acc);
        red[grp * 128 + tt] = wrow[grp * 128 + tt] * out_proj_b[tt];
        __syncthreads();
        #pragma unroll
        for (int s = 64; s > 0; s >>= 1) {
            if (tt < s) red[grp * 128 + tt] += red[grp * 128 + tt + s];
            __syncthreads();
        }
        if (tt == 0) g_b2[o] = out_b[o] + red[grp * 128];
    }
}

__device__ __forceinline__ float4 ldg4(const float* p) {
    return *reinterpret_cast<const float4*>(p);
}
// 4 halves -> 4 floats (8-byte load)
__device__ __forceinline__ void ldh4(const __half* p, float* f) {
    uint2 u = *reinterpret_cast<const uint2*>(p);
    __half2 h0 = *reinterpret_cast<__half2*>(&u.x);
    __half2 h1 = *reinterpret_cast<__half2*>(&u.y);
    float2 a = __half22float2(h0); f[0] = a.x; f[1] = a.y;
    float2 b = __half22float2(h1); f[2] = b.x; f[3] = b.y;
}
__device__ __forceinline__ void cp16(uint32_t dst, const void* src) {
    asm volatile("cp.async.cg.shared.global [%0], [%1], 16;" :: "r"(dst), "l"(src));
}
__device__ __forceinline__ float2 shfl2(float2 v, int m) {
    return make_float2(__shfl_xor_sync(0xffffffffu, v.x, m),
                       __shfl_xor_sync(0xffffffffu, v.y, m));
}

// ---------------- fused kernel: gather + MHA -> smem A tile -> fp16 mma -> out ----------------
// grid ceil(N/128); block 256 = 8 warps.
// smem layout (halves): A[128*BPITCH], then B double buffer 2 x [128*BPITCH].
#define BPITCH 136                          // halves per smem row (272 B)
#define SM_A_H 0
#define SM_B_H (128 * BPITCH)
#define FUSED_SMEM ((128 * BPITCH + 2 * 128 * BPITCH) * 2)   // 104448 bytes

__global__ void __launch_bounds__(256, 2)
fused_kernel(const int* __restrict__ dev_ids, const int* __restrict__ pse_ids,
             const int* __restrict__ attr_ids, const int* __restrict__ unit_ids,
             const float* __restrict__ values, const int* __restrict__ mask,
             const float* __restrict__ in_proj_b,
             float* __restrict__ out, int N) {
    extern __shared__ __align__(16) __half S[];
    int tid = threadIdx.x;
    int warp = tid >> 5, lane = tid & 31;
    int m0 = blockIdx.x * 128;
    uint32_t sbase = (uint32_t)__cvta_generic_to_shared(S);

    // ---- issue cp.async for B tile 0 (overlaps the entire attention phase) ----
    {
        #pragma unroll
        for (int i = 0; i < 8; ++i) {
            int idx = tid + i * 256;              // 0..2047 (128 rows x 16 chunks)
            int srow = idx >> 4, schunk = idx & 15;
            const __half* src = g_W2 + (size_t)srow * EDIM + schunk * 8;
            uint32_t dst = sbase + (uint32_t)((SM_B_H + srow * BPITCH + schunk * 8) * 2);
            cp16(dst, src);
        }
        asm volatile("cp.async.commit_group;" ::: "memory");
    }

    // ---- attention phase: this warp computes rows m0+warp*16 .. +15 into smem A ----
    {
        int d0 = lane * 4;
        int tOwn = lane & 7;
        float bq[4], bk[4], bv[4];
        { float4 t4 = ldg4(in_proj_b + d0);            bq[0]=t4.x; bq[1]=t4.y; bq[2]=t4.z; bq[3]=t4.w; }
        { float4 t4 = ldg4(in_proj_b + EDIM + d0);     bk[0]=t4.x; bk[1]=t4.y; bk[2]=t4.z; bk[3]=t4.w; }
        { float4 t4 = ldg4(in_proj_b + 2 * EDIM + d0); bv[0]=t4.x; bv[1]=t4.y; bv[2]=t4.z; bv[3]=t4.w; }
        // value-token projection vectors (row-independent): load once
        float Aq[4], Ak[4], Av_[4], Zq[4], Zk[4], Zv[4];
        ldh4(g_Avh + d0, Aq);
        ldh4(g_Avh + EDIM + d0, Ak);
        ldh4(g_Avh + 2 * EDIM + d0, Av_);
        ldh4(g_Bvh + d0, Zq);
        ldh4(g_Bvh + EDIM + d0, Zk);
        ldh4(g_Bvh + 2 * EDIM + d0, Zv);

        for (int i = 0; i < 16; ++i) {
            int lrow = warp * 16 + i;
            int n = m0 + lrow;
            float ao0 = 0.f, ao1 = 0.f, ao2 = 0.f, ao3 = 0.f;
            if (n < N) {
                float mm[5];
                #pragma unroll
                for (int t = 0; t < 5; ++t) mm[t] = (float)mask[n * 5 + t];
                int r0 = dev_ids[n];
                int r1 = 10  + pse_ids[n];
                int r2 = 20  + attr_ids[n];
                int r3 = 120 + unit_ids[n];
                float val = values[n];

                float q[5][4], k[5][4], v[5][4];
                const int ridx[4] = {r0, r1, r2, r3};
                const int tok[4] = {0, 1, 2, 4};
                #pragma unroll
                for (int ii = 0; ii < 4; ++ii) {
                    int t = tok[ii];
                    float pq[4], pk[4], pv[4];
                    ldh4(g_Pqh + ridx[ii] * EDIM + d0, pq);
                    ldh4(g_Pkh + ridx[ii] * EDIM + d0, pk);
                    ldh4(g_Pvh + ridx[ii] * EDIM + d0, pv);
                    float mt = mm[t];
                    #pragma unroll
                    for (int c = 0; c < 4; ++c) {
                        q[t][c] = fmaf(mt, pq[c], bq[c]);
                        k[t][c] = fmaf(mt, pk[c], bk[c]);
                        v[t][c] = fmaf(mt, pv[c], bv[c]);
                    }
                }
                {   // value token (t = 3)
                    float m3 = mm[3];
                    #pragma unroll
                    for (int c = 0; c < 4; ++c) {
                        q[3][c] = fmaf(m3, fmaf(val, Aq[c],  Zq[c]), bq[c]);
                        k[3][c] = fmaf(m3, fmaf(val, Ak[c],  Zk[c]), bk[c]);
                        v[3][c] = fmaf(m3, fmaf(val, Av_[c], Zv[c]), bv[c]);
                    }
                }

                // scores per head (8-lane butterfly); lane keeps only its own t-row
                float scr[5] = {0.f, 0.f, 0.f, 0.f, 0.f};
                #pragma unroll
                for (int t = 0; t < 5; ++t) {
                    #pragma unroll
                    for (int s = 0; s < 5; ++s) {
                        float p = q[t][0] * k[s][0] + q[t][1] * k[s][1]
                                + q[t][2] * k[s][2] + q[t][3] * k[s][3];
                        p += __shfl_xor_sync(0xffffffffu, p, 1);
                        p += __shfl_xor_sync(0xffffffffu, p, 2);
                        p += __shfl_xor_sync(0xffffffffu, p, 4);
                        scr[s] = (tOwn == t) ? p * 0.17677669529663687f : scr[s]; // 1/sqrt(32)
                    }
                }
                // distributed softmax (lanes 0..4 of each 8-group own one t)
                float w[5] = {0.f, 0.f, 0.f, 0.f, 0.f};
                if (tOwn < 5) {
                    float mx = scr[0];
                    #pragma unroll
                    for (int s = 1; s < 5; ++s) mx = fmaxf(mx, scr[s]);
                    float e[5], sum = 0.f;
                    #pragma unroll
                    for (int s = 0; s < 5; ++s) { e[s] = __expf(scr[s] - mx); sum += e[s]; }
                    float inv = __fdividef(1.f, sum);
                    #pragma unroll
                    for (int s = 0; s < 5; ++s) w[s] = e[s] * inv;
                }
                #pragma unroll
                for (int s = 0; s < 5; ++s) {
                    w[s] += __shfl_xor_sync(0xffffffffu, w[s], 1);
                    w[s] += __shfl_xor_sync(0xffffffffu, w[s], 2);
                    w[s] += __shfl_xor_sync(0xffffffffu, w[s], 4);
                }
                #pragma unroll
                for (int s = 0; s < 5; ++s) {
                    float ws = w[s] * 0.2f;
                    ao0 = fmaf(ws, v[s][0], ao0);
                    ao1 = fmaf(ws, v[s][1], ao1);
                    ao2 = fmaf(ws, v[s][2], ao2);
                    ao3 = fmaf(ws, v[s][3], ao3);
                }
            }
            __half2 h01 = __floats2half2_rn(ao0, ao1);
            __half2 h23 = __floats2half2_rn(ao2, ao3);
            uint2 st;
            st.x = *reinterpret_cast<uint32_t*>(&h01);
            st.y = *reinterpret_cast<uint32_t*>(&h23);
            *reinterpret_cast<uint2*>(&S[SM_A_H + lrow * BPITCH + d0]) = st;
        }
        __syncwarp();   // A rows of this warp visible to all its lanes
    }

    // ---- load A fragments from smem (warp reads only its OWN 16 rows) ----
    int g = lane >> 2;            // 0..7
    int tq = lane & 3;            // 0..3
    int mrow = m0 + warp * 16 + g;
    uint32_t a[8][4];
    {
        const __half* Ab = &S[SM_A_H + (warp * 16 + g) * BPITCH];
        #pragma unroll
        for (int s = 0; s < 8; ++s) {
            int kk = s * 16 + tq * 2;
            a[s][0] = *reinterpret_cast<const uint32_t*>(Ab + kk);
            a[s][1] = *reinterpret_cast<const uint32_t*>(Ab + 8 * BPITCH + kk);
            a[s][2] = *reinterpret_cast<const uint32_t*>(Ab + kk + 8);
            a[s][3] = *reinterpret_cast<const uint32_t*>(Ab + 8 * BPITCH + kk + 8);
        }
    }

    // ldmatrix lane addressing: 4 8x8 matrices per x4
    int brow = ((lane >> 4) << 3) + (lane & 7);   // n-row within 16-row jpair
    int bk_  = ((lane >> 3) & 1) * 8;             // k sub-offset

    // ---- GEMM loop: 6 N-tiles of 128, double-buffered B ----
    for (int nt = 0; nt < 6; ++nt) {
        asm volatile("cp.async.wait_group 0;" ::: "memory");
        __syncthreads();
        uint32_t cur = sbase + (uint32_t)((SM_B_H + (nt & 1) * 128 * BPITCH) * 2);

        // prefetch next tile into the other buffer
        if (nt < 5) {
            #pragma unroll
            for (int i = 0; i < 8; ++i) {
                int idx = tid + i * 256;
                int srow = idx >> 4, schunk = idx & 15;
                const __half* src = g_W2 + (size_t)(nt + 1) * 128 * EDIM
                                    + (size_t)srow * EDIM + schunk * 8;
                uint32_t dst = sbase + (uint32_t)((SM_B_H + ((nt + 1) & 1) * 128 * BPITCH
                                                  + srow * BPITCH + schunk * 8) * 2);
                cp16(dst, src);
            }
            asm volatile("cp.async.commit_group;" ::: "memory");
        }

        float acc[16][4];
        #pragma unroll
        for (int j = 0; j < 16; ++j)
            #pragma unroll
            for (int c = 0; c < 4; ++c) acc[j][c] = 0.f;

        #pragma unroll
        for (int s = 0; s < 8; ++s) {
            #pragma unroll
            for (int jp = 0; jp < 8; ++jp) {
                uint32_t b0, b1, b2, b3;
                uint32_t addr = cur +
                    (uint32_t)(((jp * 16 + brow) * BPITCH + s * 16 + bk_) * 2);
                asm volatile(
                    "ldmatrix.sync.aligned.m8n8.x4.shared.b16 {%0,%1,%2,%3}, [%4];"
                    : "=r"(b0), "=r"(b1), "=r"(b2), "=r"(b3) : "r"(addr));
                asm volatile(
                    "mma.sync.aligned.m16n8k16.row.col.f32.f16.f16.f32 "
                    "{%0,%1,%2,%3}, {%4,%5,%6,%7}, {%8,%9}, {%0,%1,%2,%3};"
                    : "+f"(acc[2 * jp][0]), "+f"(acc[2 * jp][1]),
                      "+f"(acc[2 * jp][2]), "+f"(acc[2 * jp][3])
                    : "r"(a[s][0]), "r"(a[s][1]), "r"(a[s][2]), "r"(a[s][3]),
                      "r"(b0), "r"(b1));
                asm volatile(
                    "mma.sync.aligned.m16n8k16.row.col.f32.f16.f16.f32 "
                    "{%0,%1,%2,%3}, {%4,%5,%6,%7}, {%8,%9}, {%0,%1,%2,%3};"
                    : "+f"(acc[2 * jp + 1][0]), "+f"(acc[2 * jp + 1][1]),
                      "+f"(acc[2 * jp + 1][2]), "+f"(acc[2 * jp + 1][3])
                    : "r"(a[s][0]), "r"(a[s][1]), "r"(a[s][2]), "r"(a[s][3]),
                      "r"(b2), "r"(b3));
            }
        }

        // ---- epilogue: bias + 4x4 float2 butterfly transpose across tq lanes ----
        // After transpose, lane (g,tq) holds 8 consecutive floats of row g(+8) for
        // j* = Jg*4+tq  -> two STG.128 fill complete 128B lines (halves store wavefronts).
        int n0 = nt * 128;
        #pragma unroll
        for (int Jg = 0; Jg < 4; ++Jg) {
            float2 bb[4];
            #pragma unroll
            for (int s = 0; s < 4; ++s)
                bb[s] = *reinterpret_cast<const float2*>(g_b2 + n0 + (Jg * 4 + s) * 8 + tq * 2);
            #pragma unroll
            for (int h = 0; h < 2; ++h) {
                int mr = mrow + 8 * h;
                float2 w0 = make_float2(acc[Jg*4+0][2*h] + bb[0].x, acc[Jg*4+0][2*h+1] + bb[0].y);
                float2 w1 = make_float2(acc[Jg*4+1][2*h] + bb[1].x, acc[Jg*4+1][2*h+1] + bb[1].y);
                float2 w2 = make_float2(acc[Jg*4+2][2*h] + bb[2].x, acc[Jg*4+2][2*h+1] + bb[2].y);
                float2 w3 = make_float2(acc[Jg*4+3][2*h] + bb[3].x, acc[Jg*4+3][2*h+1] + bb[3].y);
                // butterfly round k=1: tmp[s] = shfl_xor(w[s^1],1); flip slots with (s^tq)&1
                bool f1 = (tq & 1) != 0;
                float2 e0 = shfl2(w1, 1);
                float2 e1 = shfl2(w0, 1);
                float2 e2 = shfl2(w3, 1);
                float2 e3 = shfl2(w2, 1);
                w0 = f1 ? e0 : w0;
                w1 = f1 ? w1 : e1;
                w2 = f1 ? e2 : w2;
                w3 = f1 ? w3 : e3;
                // butterfly round k=2: tmp[s] = shfl_xor(w[s^2],2); flip slots with (s^tq)&2
                bool f2 = (tq & 2) != 0;
                float2 g0 = shfl2(w2, 2);
                float2 g1 = shfl2(w3, 2);
                float2 g2 = shfl2(w0, 2);
                float2 g3 = shfl2(w1, 2);
                w0 = f2 ? g0 : w0;
                w1 = f2 ? g1 : w1;
                w2 = f2 ? w2 : g2;
                w3 = f2 ? w3 : g3;
                if (mr < N) {
                    float* dst = out + (size_t)mr * OUTD + n0 + (Jg * 4 + tq) * 8;
                    *reinterpret_cast<float4*>(dst)     = make_float4(w0.x, w0.y, w1.x, w1.y);
                    *reinterpret_cast<float4*>(dst + 4) = make_float4(w2.x, w2.y, w3.x, w3.y);
                }
            }
        }
        __syncthreads();   // all reads of this B buffer done before it is overwritten
    }
}

extern "C" void kernel_launch(void* const* d_in, const int* in_sizes, int n_in,
                              void* d_out, int out_size) {
    (void)n_in; (void)out_size;
    const int*   dev_ids    = (const int*)  d_in[0];
    const int*   pse_ids    = (const int*)  d_in[1];
    const int*   attr_ids   = (const int*)  d_in[2];
    const int*   unit_ids   = (const int*)  d_in[3];
    const float* values     = (const float*)d_in[4];
    const int*   mask       = (const int*)  d_in[5];
    const float* dev_t      = (const float*)d_in[6];
    const float* pse_t      = (const float*)d_in[7];
    const float* attr_t     = (const float*)d_in[8];
    const float* unit_t     = (const float*)d_in[9];
    const float* val_w      = (const float*)d_in[10];
    const float* val_b      = (const float*)d_in[11];
    const float* in_proj_w  = (const float*)d_in[12];
    const float* in_proj_b  = (const float*)d_in[13];
    const float* out_proj_w = (const float*)d_in[14];
    const float* out_proj_b = (const float*)d_in[15];
    const float* out_w      = (const float*)d_in[16];
    const float* out_b      = (const float*)d_in[17];
    float* out = (float*)d_out;
    int N = in_sizes[0];
    if (N > MAXROWS) N = MAXROWS;

    cudaFuncSetAttribute(fused_kernel, cudaFuncAttributeMaxDynamicSharedMemorySize, FUSED_SMEM);

    setup_all<<<TROWS + 1 + OUTD / 3, 384>>>(dev_t, pse_t, attr_t, unit_t, in_proj_w,
                                             val_w, val_b,
                                             out_w, out_proj_w, out_proj_b, out_b);
    fused_kernel<<<(N + 127) / 128, 256, FUSED_SMEM>>>(
        dev_ids, pse_ids, attr_ids, unit_ids, values, mask, in_proj_b, out, N);
}